// round 11
// baseline (speedup 1.0000x reference)
#include <cuda_runtime.h>
#include <cstdint>
#include <cstddef>

// Problem constants
#define B_   4
#define C_   192
#define H_   128
#define W_   128
#define P_   16384
#define ND   3
#define C2   64
#define NH   2
#define HD   32
#define MQKV 576
#define SCALE 0.17677669529663687f   // 32^-0.5

// Scratch (alloc-free: __device__ globals)
__device__ float g_x  [(size_t)B_*C_*P_];     // tf32-rounded, qkv-gemm input
__device__ float g_qkv[(size_t)B_*MQKV*P_];   // fp32, attention input
__device__ float g_xo [(size_t)B_*C_*P_];     // tf32-rounded, proj-gemm input
__device__ float g_wq [(size_t)MQKV*C_];      // qkv_w: rounded + pair-permuted
__device__ float g_wp [(size_t)C_*C_];        // proj_w: rounded + pair-permuted

__device__ __forceinline__ float f2tf(float f) {
    uint32_t u;
    asm("cvt.rna.tf32.f32 %0, %1;" : "=r"(u) : "f"(f));
    return __uint_as_float(u);
}

// ---------------------------------------------------------------------------
// Stage 0: weight prep — round to tf32 and pair-permute (k,k+4) within each
// kstep-of-8 so GEMM A-fragment loads are single LDG.64.
// dst col for k: (k>>3)*8 + 2*(k&3) + ((k>>2)&1)
// ---------------------------------------------------------------------------
__global__ __launch_bounds__(256) void prep_w(
    const float* __restrict__ qkv_w, const float* __restrict__ proj_w)
{
    int i = blockIdx.x * 256 + threadIdx.x;
    if (i < MQKV * C_) {
        int m = i / C_, k = i - m * C_;
        int dc = (k >> 3) * 8 + 2 * (k & 3) + ((k >> 2) & 1);
        g_wq[(size_t)m * C_ + dc] = f2tf(qkv_w[i]);
    }
    if (i < C_ * C_) {
        int m = i / C_, k = i - m * C_;
        int dc = (k >> 3) * 8 + 2 * (k & 3) + ((k >> 2) & 1);
        g_wp[(size_t)m * C_ + dc] = f2tf(proj_w[i]);
    }
}

// ---------------------------------------------------------------------------
// Stage 1: depthwise 3x3 conv (zero pad) + residual + bias; output tf32-rounded
// ---------------------------------------------------------------------------
__global__ __launch_bounds__(256) void pos_kernel(
    const float* __restrict__ x, const float* __restrict__ pw,
    const float* __restrict__ pb)
{
    int idx = blockIdx.x * 256 + threadIdx.x;
    if (idx >= B_*C_*P_) return;
    int pix = idx & (P_-1);
    int bc  = idx >> 14;
    int c   = bc % C_;
    int y  = pix >> 7;
    int xx = pix & 127;
    const float* xb = x + (size_t)bc * P_;
    const float* w  = pw + c * 9;
    float s = x[idx];
    #pragma unroll
    for (int kh = 0; kh < 3; kh++) {
        int yy = y + kh - 1;
        if (yy < 0 || yy >= H_) continue;
        #pragma unroll
        for (int kw = 0; kw < 3; kw++) {
            int xc = xx + kw - 1;
            if (xc < 0 || xc >= W_) continue;
            s += xb[yy * W_ + xc] * w[kh * 3 + kw];
        }
    }
    g_x[idx] = f2tf(s + pb[c]);
}

// ---------------------------------------------------------------------------
// tf32 mma.sync GEMM:  Y[b, m, p] = sum_c Wm[m, c] * X[b, c, p]
// Inputs pre-rounded -> staging is a pure copy. Only B (X) lives in SMEM
// (2 x 8.5 KB double buffer). A fragments come straight from L1-resident
// pre-permuted W via LDG.64. 3 CTAs/SM.
// CTA tile 64(m) x 128(n) x 16(k); 8 warps (2m x 4n); warp tile 32x32.
// ---------------------------------------------------------------------------
#define GBM 64
#define GBN 128
#define GK  192
#define BKT 16
#define NKT 12
#define BNP 136             // Bs row stride: frag LDS conflict-free
#define BS_WORDS (BKT * BNP)    // 2176

__device__ __forceinline__ void mma_tf32(float (&d)[4], const uint32_t (&a)[4],
                                         const uint32_t (&b)[2]) {
    asm volatile(
        "mma.sync.aligned.m16n8k8.row.col.f32.tf32.tf32.f32 "
        "{%0,%1,%2,%3}, {%4,%5,%6,%7}, {%8,%9}, {%0,%1,%2,%3};"
        : "+f"(d[0]), "+f"(d[1]), "+f"(d[2]), "+f"(d[3])
        : "r"(a[0]), "r"(a[1]), "r"(a[2]), "r"(a[3]), "r"(b[0]), "r"(b[1]));
}

__global__ __launch_bounds__(256, 3) void gemm_mma(
    const float* __restrict__ Wp, const float* __restrict__ X,
    float* __restrict__ Y, int Mtot)
{
    __shared__ float Bs[2][BS_WORDS];

    int tid  = threadIdx.x;
    int lane = tid & 31;
    int wid  = tid >> 5;
    int wm   = wid & 1;             // 2 warps along m
    int wn   = wid >> 1;            // 4 warps along n
    int n0   = blockIdx.x * GBN;
    int m0   = blockIdx.y * GBM;
    int b    = blockIdx.z;
    const float* Xb = X + (size_t)b * C_ * P_;
    float* Yb = Y + (size_t)b * Mtot * P_;

    int lr = lane >> 2;
    int lc = lane & 3;

    // B staging mapping: 2 float4 per thread per tile
    int brow0 = tid >> 5;
    int brow1 = brow0 + 8;
    int bc4   = (tid & 31) << 2;
    const float* bptr0 = Xb + (size_t)brow0 * P_ + n0 + bc4;
    const float* bptr1 = Xb + (size_t)brow1 * P_ + n0 + bc4;
    int bs0 = brow0 * BNP + bc4;
    int bs1 = brow1 * BNP + bc4;

    // A fragment base rows (pre-permuted W): row r and r+8, for mt 0/1
    const float* w00 = Wp + (size_t)(m0 + wm * 32 + lr) * GK + 2 * lc;
    const float* w01 = w00 + (size_t)8  * GK;
    const float* w10 = w00 + (size_t)16 * GK;
    const float* w11 = w00 + (size_t)24 * GK;

    float4 bw0, bw1;

    // prologue: tile 0 -> Bs[0]
    bw0 = *reinterpret_cast<const float4*>(bptr0);
    bw1 = *reinterpret_cast<const float4*>(bptr1);
    *reinterpret_cast<float4*>(&Bs[0][bs0]) = bw0;
    *reinterpret_cast<float4*>(&Bs[0][bs1]) = bw1;
    __syncthreads();
    bw0 = *reinterpret_cast<const float4*>(bptr0 + (size_t)BKT * P_);
    bw1 = *reinterpret_cast<const float4*>(bptr1 + (size_t)BKT * P_);

    float acc[2][4][4];
    #pragma unroll
    for (int mt = 0; mt < 2; mt++)
        #pragma unroll
        for (int nt = 0; nt < 4; nt++)
            #pragma unroll
            for (int r = 0; r < 4; r++) acc[mt][nt][r] = 0.f;

    for (int t = 0; t < NKT; t++) {
        const uint32_t* Bsu = reinterpret_cast<const uint32_t*>(Bs[t & 1]);
        int kbase = t * BKT;

        // Load both ksteps' A fragments up front (8 independent LDG.64)
        uint2 a0[2][2], a1[2][2];
        #pragma unroll
        for (int s = 0; s < 2; s++) {
            int kk = kbase + s * 8;
            a0[s][0] = __ldg(reinterpret_cast<const uint2*>(w00 + kk));
            a0[s][1] = __ldg(reinterpret_cast<const uint2*>(w01 + kk));
            a1[s][0] = __ldg(reinterpret_cast<const uint2*>(w10 + kk));
            a1[s][1] = __ldg(reinterpret_cast<const uint2*>(w11 + kk));
        }

        #pragma unroll
        for (int s = 0; s < 2; s++) {
            uint32_t a[2][4], bf[4][2];
            a[0][0] = a0[s][0].x; a[0][2] = a0[s][0].y;
            a[0][1] = a0[s][1].x; a[0][3] = a0[s][1].y;
            a[1][0] = a1[s][0].x; a[1][2] = a1[s][0].y;
            a[1][1] = a1[s][1].x; a[1][3] = a1[s][1].y;
            #pragma unroll
            for (int nt = 0; nt < 4; nt++) {
                int c0 = (s * 8 + lc) * BNP + wn * 32 + nt * 8 + lr;
                bf[nt][0] = Bsu[c0];
                bf[nt][1] = Bsu[c0 + 4 * BNP];
            }
            #pragma unroll
            for (int mt = 0; mt < 2; mt++)
                #pragma unroll
                for (int nt = 0; nt < 4; nt++)
                    mma_tf32(acc[mt][nt], a[mt], bf[nt]);
        }

        if (t + 1 < NKT) {
            *reinterpret_cast<float4*>(&Bs[(t + 1) & 1][bs0]) = bw0;
            *reinterpret_cast<float4*>(&Bs[(t + 1) & 1][bs1]) = bw1;
        }
        __syncthreads();
        if (t + 2 < NKT) {
            int k0 = (t + 2) * BKT;
            bw0 = *reinterpret_cast<const float4*>(bptr0 + (size_t)k0 * P_);
            bw1 = *reinterpret_cast<const float4*>(bptr1 + (size_t)k0 * P_);
        }
    }

    // Epilogue: direct float2 stores from fragments
    #pragma unroll
    for (int mt = 0; mt < 2; mt++)
        #pragma unroll
        for (int nt = 0; nt < 4; nt++) {
            int r = m0 + wm * 32 + mt * 16 + lr;
            int c = n0 + wn * 32 + nt * 8 + lc * 2;
            float2 v0 = { acc[mt][nt][0], acc[mt][nt][1] };
            float2 v1 = { acc[mt][nt][2], acc[mt][nt][3] };
            *reinterpret_cast<float2*>(Yb + (size_t)r * P_ + c)       = v0;
            *reinterpret_cast<float2*>(Yb + (size_t)(r + 8) * P_ + c) = v1;
        }
}

// ---------------------------------------------------------------------------
// Stage 3: multi-dilate window attention; output tf32-rounded (proj input)
// ---------------------------------------------------------------------------
__device__ __forceinline__ int reflect_i(int t, int n) {
    return t < 0 ? -t : (t >= n ? 2*n - 2 - t : t);
}

__global__ __launch_bounds__(256) void attn_kernel()
{
    int p    = blockIdx.x * 256 + threadIdx.x;
    int head = blockIdx.y & 1;
    int dil  = blockIdx.y >> 1;
    int b    = blockIdx.z;
    int dl   = dil + 1;

    int y  = p >> 7;
    int xx = p & 127;

    int nb[9];
    #pragma unroll
    for (int jy = 0; jy < 3; jy++) {
        int yy = reflect_i(y + (jy-1)*dl, H_);
        #pragma unroll
        for (int jx = 0; jx < 3; jx++) {
            int xc = reflect_i(xx + (jx-1)*dl, W_);
            nb[jy*3 + jx] = yy * W_ + xc;
        }
    }

    size_t chan0 = (size_t)b * MQKV + dil * C2 + head * HD;
    const float* qp = g_qkv + chan0 * P_;
    const float* kp = g_qkv + (chan0 + (size_t)C_)   * P_;
    const float* vp = g_qkv + (chan0 + (size_t)2*C_) * P_;

    float sc[9];
    #pragma unroll
    for (int j = 0; j < 9; j++) sc[j] = 0.f;

    #pragma unroll 4
    for (int d = 0; d < HD; d++) {
        float qd = qp[(size_t)d * P_ + p];
        const float* kr = kp + (size_t)d * P_;
        #pragma unroll
        for (int j = 0; j < 9; j++) sc[j] += qd * kr[nb[j]];
    }

    float mx = sc[0] * SCALE;
    #pragma unroll
    for (int j = 0; j < 9; j++) { sc[j] *= SCALE; mx = fmaxf(mx, sc[j]); }
    float sum = 0.f;
    #pragma unroll
    for (int j = 0; j < 9; j++) { sc[j] = __expf(sc[j] - mx); sum += sc[j]; }
    float inv = 1.f / sum;

    float* op = g_xo + ((size_t)b * C_ + dil * C2 + head * HD) * P_ + p;
    #pragma unroll 4
    for (int d = 0; d < HD; d++) {
        const float* vr = vp + (size_t)d * P_;
        float a = 0.f;
        #pragma unroll
        for (int j = 0; j < 9; j++) a += sc[j] * vr[nb[j]];
        op[(size_t)d * P_] = f2tf(a * inv);
    }
}

// ---------------------------------------------------------------------------
extern "C" void kernel_launch(void* const* d_in, const int* in_sizes, int n_in,
                              void* d_out, int out_size)
{
    const float* x      = (const float*)d_in[0];
    const float* pos_w  = (const float*)d_in[1];
    const float* pos_b  = (const float*)d_in[2];
    const float* qkv_w  = (const float*)d_in[3];
    const float* proj_w = (const float*)d_in[4];
    float* out = (float*)d_out;

    float *gx, *gq, *go, *gwq, *gwp;
    cudaGetSymbolAddress((void**)&gx,  g_x);
    cudaGetSymbolAddress((void**)&gq,  g_qkv);
    cudaGetSymbolAddress((void**)&go,  g_xo);
    cudaGetSymbolAddress((void**)&gwq, g_wq);
    cudaGetSymbolAddress((void**)&gwp, g_wp);

    // Stage 0: weight prep (round + pair-permute)
    prep_w<<<(MQKV*C_ + 255)/256, 256>>>(qkv_w, proj_w);

    // Stage 1: positional dwconv + residual + bias
    {
        int total = B_*C_*P_;
        pos_kernel<<<(total + 255)/256, 256>>>(x, pos_w, pos_b);
    }
    // Stage 2: qkv 1x1 conv (576 x 192 x 16384 per batch)
    {
        dim3 grid(P_/GBN, MQKV/GBM, B_);
        gemm_mma<<<grid, 256>>>(gwq, gx, gq, MQKV);
    }
    // Stage 3: attention
    {
        dim3 grid(P_/256, NH*ND, B_);
        attn_kernel<<<grid, 256>>>();
    }
    // Stage 4: projection (192 x 192 x 16384 per batch)
    {
        dim3 grid(P_/GBN, C_/GBM, B_);
        gemm_mma<<<grid, 256>>>(gwp, go, out, C_);
    }
}

// round 12
// speedup vs baseline: 1.1341x; 1.1341x over previous
#include <cuda_runtime.h>
#include <cstdint>
#include <cstddef>

// Problem constants
#define B_   4
#define C_   192
#define H_   128
#define W_   128
#define P_   16384
#define ND   3
#define C2   64
#define NH   2
#define HD   32
#define MQKV 576
#define SCALE 0.17677669529663687f   // 32^-0.5

// Scratch (alloc-free: __device__ globals)
__device__ float g_x  [(size_t)B_*C_*P_];     // tf32-rounded, qkv-gemm input
__device__ float g_qkv[(size_t)B_*MQKV*P_];   // fp32, attention input
__device__ float g_xo [(size_t)B_*C_*P_];     // tf32-rounded, proj-gemm input
__device__ float g_wq [(size_t)MQKV*C_];      // qkv_w: rounded + pair-permuted
__device__ float g_wp [(size_t)C_*C_];        // proj_w: rounded + pair-permuted

__device__ __forceinline__ float f2tf(float f) {
    uint32_t u;
    asm("cvt.rna.tf32.f32 %0, %1;" : "=r"(u) : "f"(f));
    return __uint_as_float(u);
}

// ---------------------------------------------------------------------------
// Stage 0: weight prep — round to tf32 and pair-permute (k,k+4) within each
// kstep-of-8 so A fragment LDS are 64-bit.
// dst col for k: (k>>3)*8 + 2*(k&3) + ((k>>2)&1)
// ---------------------------------------------------------------------------
__global__ __launch_bounds__(256) void prep_w(
    const float* __restrict__ qkv_w, const float* __restrict__ proj_w)
{
    int i = blockIdx.x * 256 + threadIdx.x;
    if (i < MQKV * C_) {
        int m = i / C_, k = i - m * C_;
        int dc = (k >> 3) * 8 + 2 * (k & 3) + ((k >> 2) & 1);
        g_wq[(size_t)m * C_ + dc] = f2tf(qkv_w[i]);
    }
    if (i < C_ * C_) {
        int m = i / C_, k = i - m * C_;
        int dc = (k >> 3) * 8 + 2 * (k & 3) + ((k >> 2) & 1);
        g_wp[(size_t)m * C_ + dc] = f2tf(proj_w[i]);
    }
}

// ---------------------------------------------------------------------------
// Stage 1: depthwise 3x3 conv (zero pad) + residual + bias; output tf32-rounded
// ---------------------------------------------------------------------------
__global__ __launch_bounds__(256) void pos_kernel(
    const float* __restrict__ x, const float* __restrict__ pw,
    const float* __restrict__ pb)
{
    int idx = blockIdx.x * 256 + threadIdx.x;
    if (idx >= B_*C_*P_) return;
    int pix = idx & (P_-1);
    int bc  = idx >> 14;
    int c   = bc % C_;
    int y  = pix >> 7;
    int xx = pix & 127;
    const float* xb = x + (size_t)bc * P_;
    const float* w  = pw + c * 9;
    float s = x[idx];
    #pragma unroll
    for (int kh = 0; kh < 3; kh++) {
        int yy = y + kh - 1;
        if (yy < 0 || yy >= H_) continue;
        #pragma unroll
        for (int kw = 0; kw < 3; kw++) {
            int xc = xx + kw - 1;
            if (xc < 0 || xc >= W_) continue;
            s += xb[yy * W_ + xc] * w[kh * 3 + kw];
        }
    }
    g_x[idx] = f2tf(s + pb[c]);
}

// ---------------------------------------------------------------------------
// tf32 mma.sync GEMM (pre-rounded inputs -> staging is pure copy, no cvt).
// CTA tile 64(m) x 128(n) x 16(k); double-buffered smem (29.7 KB); 3 CTAs/SM.
// 8 warps (2m x 4n); warp tile 32x32 via m16n8k8 tf32 HMMA.
// A pair-permuted in gmem -> frag loads LDS.64, conflict-free at AP=24.
// ---------------------------------------------------------------------------
#define GBM 64
#define GBN 128
#define GK  192
#define BKT 16
#define NKT 12
#define AP  24
#define BNP 136
#define AS_WORDS (GBM * AP)     // 1536
#define BS_WORDS (BKT * BNP)    // 2176

__device__ __forceinline__ void mma_tf32(float (&d)[4], const uint32_t (&a)[4],
                                         const uint32_t (&b)[2]) {
    asm volatile(
        "mma.sync.aligned.m16n8k8.row.col.f32.tf32.tf32.f32 "
        "{%0,%1,%2,%3}, {%4,%5,%6,%7}, {%8,%9}, {%0,%1,%2,%3};"
        : "+f"(d[0]), "+f"(d[1]), "+f"(d[2]), "+f"(d[3])
        : "r"(a[0]), "r"(a[1]), "r"(a[2]), "r"(a[3]), "r"(b[0]), "r"(b[1]));
}

__global__ __launch_bounds__(256, 3) void gemm_mma(
    const float* __restrict__ Wp, const float* __restrict__ X,
    float* __restrict__ Y, int Mtot)
{
    __shared__ float As[2][AS_WORDS];
    __shared__ float Bs[2][BS_WORDS];

    int tid  = threadIdx.x;
    int lane = tid & 31;
    int wid  = tid >> 5;
    int wm   = wid & 1;
    int wn   = wid >> 1;
    int n0   = blockIdx.x * GBN;
    int m0   = blockIdx.y * GBM;
    int b    = blockIdx.z;
    const float* Xb = X + (size_t)b * C_ * P_;
    float* Yb = Y + (size_t)b * Mtot * P_;

    int lr = lane >> 2;
    int lc = lane & 3;

    // A staging: 1 float4/thread. Pure copy (already rounded+permuted).
    int arow = tid >> 2;
    int a4   = (tid & 3) << 2;
    const float* aptr = Wp + (size_t)(m0 + arow) * GK + a4;
    int as_off = arow * AP + a4;
    // B staging: 2 float4/thread.
    int brow0 = tid >> 5;
    int brow1 = brow0 + 8;
    int bc4   = (tid & 31) << 2;
    const float* bptr0 = Xb + (size_t)brow0 * P_ + n0 + bc4;
    const float* bptr1 = Xb + (size_t)brow1 * P_ + n0 + bc4;
    int bs0 = brow0 * BNP + bc4;
    int bs1 = brow1 * BNP + bc4;

    float4 aw, bw0, bw1;

    // prologue: tile 0 -> buf 0
    aw  = *reinterpret_cast<const float4*>(aptr);
    bw0 = *reinterpret_cast<const float4*>(bptr0);
    bw1 = *reinterpret_cast<const float4*>(bptr1);
    *reinterpret_cast<float4*>(&As[0][as_off]) = aw;
    *reinterpret_cast<float4*>(&Bs[0][bs0])    = bw0;
    *reinterpret_cast<float4*>(&Bs[0][bs1])    = bw1;
    __syncthreads();
    aw  = *reinterpret_cast<const float4*>(aptr + BKT);
    bw0 = *reinterpret_cast<const float4*>(bptr0 + (size_t)BKT * P_);
    bw1 = *reinterpret_cast<const float4*>(bptr1 + (size_t)BKT * P_);

    float acc[2][4][4];
    #pragma unroll
    for (int mt = 0; mt < 2; mt++)
        #pragma unroll
        for (int nt = 0; nt < 4; nt++)
            #pragma unroll
            for (int r = 0; r < 4; r++) acc[mt][nt][r] = 0.f;

    for (int t = 0; t < NKT; t++) {
        const float* Asb = As[t & 1];
        const uint32_t* Bsu = reinterpret_cast<const uint32_t*>(Bs[t & 1]);

        #pragma unroll
        for (int s = 0; s < 2; s++) {
            uint32_t a[2][4], bf[4][2];
            #pragma unroll
            for (int mt = 0; mt < 2; mt++) {
                int r = wm * 32 + mt * 16 + lr;
                uint2 u0 = *reinterpret_cast<const uint2*>(Asb + r * AP + s * 8 + 2 * lc);
                uint2 u1 = *reinterpret_cast<const uint2*>(Asb + (r + 8) * AP + s * 8 + 2 * lc);
                a[mt][0] = u0.x; a[mt][2] = u0.y;
                a[mt][1] = u1.x; a[mt][3] = u1.y;
            }
            #pragma unroll
            for (int nt = 0; nt < 4; nt++) {
                int c0 = (s * 8 + lc) * BNP + wn * 32 + nt * 8 + lr;
                bf[nt][0] = Bsu[c0];
                bf[nt][1] = Bsu[c0 + 4 * BNP];
            }
            #pragma unroll
            for (int mt = 0; mt < 2; mt++)
                #pragma unroll
                for (int nt = 0; nt < 4; nt++)
                    mma_tf32(acc[mt][nt], a[mt], bf[nt]);
        }

        if (t + 1 < NKT) {
            *reinterpret_cast<float4*>(&As[(t + 1) & 1][as_off]) = aw;
            *reinterpret_cast<float4*>(&Bs[(t + 1) & 1][bs0])    = bw0;
            *reinterpret_cast<float4*>(&Bs[(t + 1) & 1][bs1])    = bw1;
        }
        __syncthreads();
        if (t + 2 < NKT) {
            int k0 = (t + 2) * BKT;
            aw  = *reinterpret_cast<const float4*>(aptr + k0);
            bw0 = *reinterpret_cast<const float4*>(bptr0 + (size_t)k0 * P_);
            bw1 = *reinterpret_cast<const float4*>(bptr1 + (size_t)k0 * P_);
        }
    }

    #pragma unroll
    for (int mt = 0; mt < 2; mt++)
        #pragma unroll
        for (int nt = 0; nt < 4; nt++) {
            int r = m0 + wm * 32 + mt * 16 + lr;
            int c = n0 + wn * 32 + nt * 8 + lc * 2;
            float2 v0 = { acc[mt][nt][0], acc[mt][nt][1] };
            float2 v1 = { acc[mt][nt][2], acc[mt][nt][3] };
            *reinterpret_cast<float2*>(Yb + (size_t)r * P_ + c)       = v0;
            *reinterpret_cast<float2*>(Yb + (size_t)(r + 8) * P_ + c) = v1;
        }
}

// ---------------------------------------------------------------------------
// Stage 3: attention, 2-way channel split per pixel.
// Block = 128 pixels x 2 halves; halves exchange partial scores via smem
// (stride 9 -> gcd(9,32)=1, conflict-free). Output tf32-rounded.
// ---------------------------------------------------------------------------
#define APX 128
#define HHD 16     // channels per half

__device__ __forceinline__ int reflect_i(int t, int n) {
    return t < 0 ? -t : (t >= n ? 2*n - 2 - t : t);
}

__global__ __launch_bounds__(256) void attn_kernel()
{
    __shared__ float ssc[2][APX * 9];

    int tid  = threadIdx.x;
    int half = tid >> 7;
    int px   = tid & 127;
    int p    = blockIdx.x * APX + px;
    int head = blockIdx.y & 1;
    int dil  = blockIdx.y >> 1;
    int b    = blockIdx.z;
    int dl   = dil + 1;

    int y  = p >> 7;
    int xx = p & 127;

    int nb[9];
    #pragma unroll
    for (int jy = 0; jy < 3; jy++) {
        int yy = reflect_i(y + (jy-1)*dl, H_);
        #pragma unroll
        for (int jx = 0; jx < 3; jx++) {
            int xc = reflect_i(xx + (jx-1)*dl, W_);
            nb[jy*3 + jx] = yy * W_ + xc;
        }
    }

    size_t chan0 = (size_t)b * MQKV + dil * C2 + head * HD + half * HHD;
    const float* qp = g_qkv + chan0 * P_;
    const float* kp = g_qkv + (chan0 + (size_t)C_)   * P_;
    const float* vp = g_qkv + (chan0 + (size_t)2*C_) * P_;

    float sc[9];
    #pragma unroll
    for (int j = 0; j < 9; j++) sc[j] = 0.f;

    #pragma unroll 4
    for (int d = 0; d < HHD; d++) {
        float qd = qp[(size_t)d * P_ + p];
        const float* kr = kp + (size_t)d * P_;
        #pragma unroll
        for (int j = 0; j < 9; j++) sc[j] += qd * kr[nb[j]];
    }

    // exchange partial scores between halves
    {
        float* mine = &ssc[half][px * 9];
        #pragma unroll
        for (int j = 0; j < 9; j++) mine[j] = sc[j];
    }
    __syncthreads();
    {
        const float* other = &ssc[half ^ 1][px * 9];
        #pragma unroll
        for (int j = 0; j < 9; j++) sc[j] += other[j];
    }

    // softmax over 9 (computed redundantly by both halves)
    float mx = sc[0] * SCALE;
    #pragma unroll
    for (int j = 0; j < 9; j++) { sc[j] *= SCALE; mx = fmaxf(mx, sc[j]); }
    float sum = 0.f;
    #pragma unroll
    for (int j = 0; j < 9; j++) { sc[j] = __expf(sc[j] - mx); sum += sc[j]; }
    float inv = 1.f / sum;

    float* op = g_xo + ((size_t)b * C_ + dil * C2 + head * HD + half * HHD) * P_ + p;
    #pragma unroll 4
    for (int d = 0; d < HHD; d++) {
        const float* vr = vp + (size_t)d * P_;
        float a = 0.f;
        #pragma unroll
        for (int j = 0; j < 9; j++) a += sc[j] * vr[nb[j]];
        op[(size_t)d * P_] = f2tf(a * inv);
    }
}

// ---------------------------------------------------------------------------
extern "C" void kernel_launch(void* const* d_in, const int* in_sizes, int n_in,
                              void* d_out, int out_size)
{
    const float* x      = (const float*)d_in[0];
    const float* pos_w  = (const float*)d_in[1];
    const float* pos_b  = (const float*)d_in[2];
    const float* qkv_w  = (const float*)d_in[3];
    const float* proj_w = (const float*)d_in[4];
    float* out = (float*)d_out;

    float *gx, *gq, *go, *gwq, *gwp;
    cudaGetSymbolAddress((void**)&gx,  g_x);
    cudaGetSymbolAddress((void**)&gq,  g_qkv);
    cudaGetSymbolAddress((void**)&go,  g_xo);
    cudaGetSymbolAddress((void**)&gwq, g_wq);
    cudaGetSymbolAddress((void**)&gwp, g_wp);

    // Stage 0: weight prep (round + pair-permute)
    prep_w<<<(MQKV*C_ + 255)/256, 256>>>(qkv_w, proj_w);

    // Stage 1: positional dwconv + residual + bias
    {
        int total = B_*C_*P_;
        pos_kernel<<<(total + 255)/256, 256>>>(x, pos_w, pos_b);
    }
    // Stage 2: qkv 1x1 conv (576 x 192 x 16384 per batch)
    {
        dim3 grid(P_/GBN, MQKV/GBM, B_);
        gemm_mma<<<grid, 256>>>(gwq, gx, gq, MQKV);
    }
    // Stage 3: attention (channel-split 2-way)
    {
        dim3 grid(P_/APX, NH*ND, B_);
        attn_kernel<<<grid, 256>>>();
    }
    // Stage 4: projection (192 x 192 x 16384 per batch)
    {
        dim3 grid(P_/GBN, C_/GBM, B_);
        gemm_mma<<<grid, 256>>>(gwp, go, out, C_);
    }
}

// round 13
// speedup vs baseline: 1.2865x; 1.1344x over previous
#include <cuda_runtime.h>
#include <cstdint>
#include <cstddef>

// Problem constants
#define B_   4
#define C_   192
#define H_   128
#define W_   128
#define P_   16384
#define ND   3
#define C2   64
#define NH   2
#define HD   32
#define MQKV 576
#define SCALE 0.17677669529663687f   // 32^-0.5

// Scratch (alloc-free: __device__ globals)
__device__ float g_x  [(size_t)B_*C_*P_];     // tf32-rounded, qkv-gemm input
__device__ float g_qkv[(size_t)B_*MQKV*P_];   // fp32, attention input
__device__ float g_xo [(size_t)B_*C_*P_];     // tf32-rounded, proj-gemm input
__device__ float g_wq [(size_t)MQKV*C_];      // qkv_w: rounded + pair-permuted
__device__ float g_wp [(size_t)C_*C_];        // proj_w: rounded + pair-permuted

__device__ __forceinline__ float f2tf(float f) {
    uint32_t u;
    asm("cvt.rna.tf32.f32 %0, %1;" : "=r"(u) : "f"(f));
    return __uint_as_float(u);
}

// ---------------------------------------------------------------------------
// Stage 0: weight prep — round to tf32 and pair-permute (k,k+4) per kstep-of-8
// ---------------------------------------------------------------------------
__global__ __launch_bounds__(256) void prep_w(
    const float* __restrict__ qkv_w, const float* __restrict__ proj_w)
{
    int i = blockIdx.x * 256 + threadIdx.x;
    if (i < MQKV * C_) {
        int m = i / C_, k = i - m * C_;
        int dc = (k >> 3) * 8 + 2 * (k & 3) + ((k >> 2) & 1);
        g_wq[(size_t)m * C_ + dc] = f2tf(qkv_w[i]);
    }
    if (i < C_ * C_) {
        int m = i / C_, k = i - m * C_;
        int dc = (k >> 3) * 8 + 2 * (k & 3) + ((k >> 2) & 1);
        g_wp[(size_t)m * C_ + dc] = f2tf(proj_w[i]);
    }
}

// ---------------------------------------------------------------------------
// Stage 1: depthwise 3x3 conv (zero pad) + residual + bias; output tf32-rounded
// ---------------------------------------------------------------------------
__global__ __launch_bounds__(256) void pos_kernel(
    const float* __restrict__ x, const float* __restrict__ pw,
    const float* __restrict__ pb)
{
    int idx = blockIdx.x * 256 + threadIdx.x;
    if (idx >= B_*C_*P_) return;
    int pix = idx & (P_-1);
    int bc  = idx >> 14;
    int c   = bc % C_;
    int y  = pix >> 7;
    int xx = pix & 127;
    const float* xb = x + (size_t)bc * P_;
    const float* w  = pw + c * 9;
    float s = x[idx];
    #pragma unroll
    for (int kh = 0; kh < 3; kh++) {
        int yy = y + kh - 1;
        if (yy < 0 || yy >= H_) continue;
        #pragma unroll
        for (int kw = 0; kw < 3; kw++) {
            int xc = xx + kw - 1;
            if (xc < 0 || xc >= W_) continue;
            s += xb[yy * W_ + xc] * w[kh * 3 + kw];
        }
    }
    g_x[idx] = f2tf(s + pb[c]);
}

// ---------------------------------------------------------------------------
// tf32 mma.sync GEMM (pre-rounded inputs -> staging is pure copy, no cvt).
// CTA tile 64(m) x 128(n) x 16(k); double-buffered smem; 3 CTAs/SM.
// ---------------------------------------------------------------------------
#define GBM 64
#define GBN 128
#define GK  192
#define BKT 16
#define NKT 12
#define AP  24
#define BNP 136
#define AS_WORDS (GBM * AP)
#define BS_WORDS (BKT * BNP)

__device__ __forceinline__ void mma_tf32(float (&d)[4], const uint32_t (&a)[4],
                                         const uint32_t (&b)[2]) {
    asm volatile(
        "mma.sync.aligned.m16n8k8.row.col.f32.tf32.tf32.f32 "
        "{%0,%1,%2,%3}, {%4,%5,%6,%7}, {%8,%9}, {%0,%1,%2,%3};"
        : "+f"(d[0]), "+f"(d[1]), "+f"(d[2]), "+f"(d[3])
        : "r"(a[0]), "r"(a[1]), "r"(a[2]), "r"(a[3]), "r"(b[0]), "r"(b[1]));
}

__global__ __launch_bounds__(256, 3) void gemm_mma(
    const float* __restrict__ Wp, const float* __restrict__ X,
    float* __restrict__ Y, int Mtot)
{
    __shared__ float As[2][AS_WORDS];
    __shared__ float Bs[2][BS_WORDS];

    int tid  = threadIdx.x;
    int lane = tid & 31;
    int wid  = tid >> 5;
    int wm   = wid & 1;
    int wn   = wid >> 1;
    int n0   = blockIdx.x * GBN;
    int m0   = blockIdx.y * GBM;
    int b    = blockIdx.z;
    const float* Xb = X + (size_t)b * C_ * P_;
    float* Yb = Y + (size_t)b * Mtot * P_;

    int lr = lane >> 2;
    int lc = lane & 3;

    int arow = tid >> 2;
    int a4   = (tid & 3) << 2;
    const float* aptr = Wp + (size_t)(m0 + arow) * GK + a4;
    int as_off = arow * AP + a4;
    int brow0 = tid >> 5;
    int brow1 = brow0 + 8;
    int bc4   = (tid & 31) << 2;
    const float* bptr0 = Xb + (size_t)brow0 * P_ + n0 + bc4;
    const float* bptr1 = Xb + (size_t)brow1 * P_ + n0 + bc4;
    int bs0 = brow0 * BNP + bc4;
    int bs1 = brow1 * BNP + bc4;

    float4 aw, bw0, bw1;

    aw  = *reinterpret_cast<const float4*>(aptr);
    bw0 = *reinterpret_cast<const float4*>(bptr0);
    bw1 = *reinterpret_cast<const float4*>(bptr1);
    *reinterpret_cast<float4*>(&As[0][as_off]) = aw;
    *reinterpret_cast<float4*>(&Bs[0][bs0])    = bw0;
    *reinterpret_cast<float4*>(&Bs[0][bs1])    = bw1;
    __syncthreads();
    aw  = *reinterpret_cast<const float4*>(aptr + BKT);
    bw0 = *reinterpret_cast<const float4*>(bptr0 + (size_t)BKT * P_);
    bw1 = *reinterpret_cast<const float4*>(bptr1 + (size_t)BKT * P_);

    float acc[2][4][4];
    #pragma unroll
    for (int mt = 0; mt < 2; mt++)
        #pragma unroll
        for (int nt = 0; nt < 4; nt++)
            #pragma unroll
            for (int r = 0; r < 4; r++) acc[mt][nt][r] = 0.f;

    for (int t = 0; t < NKT; t++) {
        const float* Asb = As[t & 1];
        const uint32_t* Bsu = reinterpret_cast<const uint32_t*>(Bs[t & 1]);

        #pragma unroll
        for (int s = 0; s < 2; s++) {
            uint32_t a[2][4], bf[4][2];
            #pragma unroll
            for (int mt = 0; mt < 2; mt++) {
                int r = wm * 32 + mt * 16 + lr;
                uint2 u0 = *reinterpret_cast<const uint2*>(Asb + r * AP + s * 8 + 2 * lc);
                uint2 u1 = *reinterpret_cast<const uint2*>(Asb + (r + 8) * AP + s * 8 + 2 * lc);
                a[mt][0] = u0.x; a[mt][2] = u0.y;
                a[mt][1] = u1.x; a[mt][3] = u1.y;
            }
            #pragma unroll
            for (int nt = 0; nt < 4; nt++) {
                int c0 = (s * 8 + lc) * BNP + wn * 32 + nt * 8 + lr;
                bf[nt][0] = Bsu[c0];
                bf[nt][1] = Bsu[c0 + 4 * BNP];
            }
            #pragma unroll
            for (int mt = 0; mt < 2; mt++)
                #pragma unroll
                for (int nt = 0; nt < 4; nt++)
                    mma_tf32(acc[mt][nt], a[mt], bf[nt]);
        }

        if (t + 1 < NKT) {
            *reinterpret_cast<float4*>(&As[(t + 1) & 1][as_off]) = aw;
            *reinterpret_cast<float4*>(&Bs[(t + 1) & 1][bs0])    = bw0;
            *reinterpret_cast<float4*>(&Bs[(t + 1) & 1][bs1])    = bw1;
        }
        __syncthreads();
        if (t + 2 < NKT) {
            int k0 = (t + 2) * BKT;
            aw  = *reinterpret_cast<const float4*>(aptr + k0);
            bw0 = *reinterpret_cast<const float4*>(bptr0 + (size_t)k0 * P_);
            bw1 = *reinterpret_cast<const float4*>(bptr1 + (size_t)k0 * P_);
        }
    }

    #pragma unroll
    for (int mt = 0; mt < 2; mt++)
        #pragma unroll
        for (int nt = 0; nt < 4; nt++) {
            int r = m0 + wm * 32 + mt * 16 + lr;
            int c = n0 + wn * 32 + nt * 8 + lc * 2;
            float2 v0 = { acc[mt][nt][0], acc[mt][nt][1] };
            float2 v1 = { acc[mt][nt][2], acc[mt][nt][3] };
            *reinterpret_cast<float2*>(Yb + (size_t)r * P_ + c)       = v0;
            *reinterpret_cast<float2*>(Yb + (size_t)(r + 8) * P_ + c) = v1;
        }
}

// ---------------------------------------------------------------------------
// Stage 3: attention via SMEM row-staging.
// Block = one image row (128 px) x one (b, dil, head). 256 threads =
// 2 channel-halves x 128 px. K rows (3 reflected y-rows x 32 ch) staged into
// a 48 KB smem tile with LDG.128; scores from LDS; then V re-staged into the
// SAME buffer for the output pass. Score exchange/order identical to before.
// ---------------------------------------------------------------------------
#define HHD 16
#define KV_WORDS (HD * 3 * W_)          // 12288 floats (48 KB)
#define ATT_SMEM ((KV_WORDS + 2 * W_ * 9) * 4)   // + ssc 9216 B = 58368 B

__device__ __forceinline__ int reflect_i(int t, int n) {
    return t < 0 ? -t : (t >= n ? 2*n - 2 - t : t);
}

__global__ __launch_bounds__(256) void attn_kernel()
{
    extern __shared__ float asm_[];
    float* kv  = asm_;                 // [32 ch][3 rows][128 x]
    float* ssc = asm_ + KV_WORDS;      // [2][128*9]

    int tid  = threadIdx.x;
    int half = tid >> 7;
    int px   = tid & 127;
    int y    = blockIdx.x;
    int head = blockIdx.y & 1;
    int dil  = blockIdx.y >> 1;
    int b    = blockIdx.z;
    int dl   = dil + 1;
    int p    = y * W_ + px;

    // reflected x offsets (for smem reads)
    int xs[3];
    #pragma unroll
    for (int jx = 0; jx < 3; jx++)
        xs[jx] = reflect_i(px + (jx - 1) * dl, W_);
    // reflected y rows (for staging)
    int ys[3];
    #pragma unroll
    for (int jy = 0; jy < 3; jy++)
        ys[jy] = reflect_i(y + (jy - 1) * dl, H_);

    size_t chan0 = (size_t)b * MQKV + dil * C2 + head * HD;    // 32-ch base
    const float* qp = g_qkv + (chan0 + (size_t)half * HHD) * P_;
    const float* kp = g_qkv + (chan0 + (size_t)C_)   * P_;
    const float* vp = g_qkv + (chan0 + (size_t)2*C_) * P_;

    // --- Stage K: 96 (ch,row) pairs x 128 floats = 3072 float4s, 12/thread ---
    #pragma unroll
    for (int i = 0; i < 12; i++) {
        int u    = tid + i * 256;
        int pair = u >> 5;
        int x4   = (u & 31) << 2;
        int ch   = pair / 3;
        int jy   = pair - ch * 3;
        float4 v = *reinterpret_cast<const float4*>(
            kp + (size_t)ch * P_ + ys[jy] * W_ + x4);
        *reinterpret_cast<float4*>(kv + pair * W_ + x4) = v;
    }
    __syncthreads();

    // --- Scores from smem (this half's 16 channels) ---
    float sc[9];
    #pragma unroll
    for (int j = 0; j < 9; j++) sc[j] = 0.f;

    #pragma unroll 4
    for (int d = 0; d < HHD; d++) {
        float qd = qp[(size_t)d * P_ + p];
        const float* kb = kv + (half * HHD + d) * 3 * W_;
        #pragma unroll
        for (int jy = 0; jy < 3; jy++) {
            const float* kr = kb + jy * W_;
            #pragma unroll
            for (int jx = 0; jx < 3; jx++)
                sc[jy*3 + jx] += qd * kr[xs[jx]];
        }
    }

    // exchange partial scores between halves
    {
        float* mine = &ssc[half * (W_ * 9) + px * 9];
        #pragma unroll
        for (int j = 0; j < 9; j++) mine[j] = sc[j];
    }
    __syncthreads();
    {
        const float* other = &ssc[(half ^ 1) * (W_ * 9) + px * 9];
        #pragma unroll
        for (int j = 0; j < 9; j++) sc[j] += other[j];
    }

    // softmax over 9 (redundant per half)
    float mx = sc[0] * SCALE;
    #pragma unroll
    for (int j = 0; j < 9; j++) { sc[j] *= SCALE; mx = fmaxf(mx, sc[j]); }
    float sum = 0.f;
    #pragma unroll
    for (int j = 0; j < 9; j++) { sc[j] = __expf(sc[j] - mx); sum += sc[j]; }
    float inv = 1.f / sum;

    // --- Stage V into the same buffer (k reads all completed pre-sync) ---
    #pragma unroll
    for (int i = 0; i < 12; i++) {
        int u    = tid + i * 256;
        int pair = u >> 5;
        int x4   = (u & 31) << 2;
        int ch   = pair / 3;
        int jy   = pair - ch * 3;
        float4 v = *reinterpret_cast<const float4*>(
            vp + (size_t)ch * P_ + ys[jy] * W_ + x4);
        *reinterpret_cast<float4*>(kv + pair * W_ + x4) = v;
    }
    __syncthreads();

    // --- Output pass (this half's 16 channels) ---
    float* op = g_xo + (chan0 - (size_t)b * MQKV + (size_t)b * C_
                        + (size_t)half * HHD) * P_ + p;
    #pragma unroll 4
    for (int d = 0; d < HHD; d++) {
        const float* vb = kv + (half * HHD + d) * 3 * W_;
        float a = 0.f;
        #pragma unroll
        for (int jy = 0; jy < 3; jy++) {
            const float* vr = vb + jy * W_;
            #pragma unroll
            for (int jx = 0; jx < 3; jx++)
                a += sc[jy*3 + jx] * vr[xs[jx]];
        }
        op[(size_t)d * P_] = f2tf(a * inv);
    }
}

// ---------------------------------------------------------------------------
extern "C" void kernel_launch(void* const* d_in, const int* in_sizes, int n_in,
                              void* d_out, int out_size)
{
    const float* x      = (const float*)d_in[0];
    const float* pos_w  = (const float*)d_in[1];
    const float* pos_b  = (const float*)d_in[2];
    const float* qkv_w  = (const float*)d_in[3];
    const float* proj_w = (const float*)d_in[4];
    float* out = (float*)d_out;

    float *gx, *gq, *go, *gwq, *gwp;
    cudaGetSymbolAddress((void**)&gx,  g_x);
    cudaGetSymbolAddress((void**)&gq,  g_qkv);
    cudaGetSymbolAddress((void**)&go,  g_xo);
    cudaGetSymbolAddress((void**)&gwq, g_wq);
    cudaGetSymbolAddress((void**)&gwp, g_wp);

    cudaFuncSetAttribute(attn_kernel, cudaFuncAttributeMaxDynamicSharedMemorySize, ATT_SMEM);

    // Stage 0: weight prep (round + pair-permute)
    prep_w<<<(MQKV*C_ + 255)/256, 256>>>(qkv_w, proj_w);

    // Stage 1: positional dwconv + residual + bias
    {
        int total = B_*C_*P_;
        pos_kernel<<<(total + 255)/256, 256>>>(x, pos_w, pos_b);
    }
    // Stage 2: qkv 1x1 conv (576 x 192 x 16384 per batch)
    {
        dim3 grid(P_/GBN, MQKV/GBM, B_);
        gemm_mma<<<grid, 256>>>(gwq, gx, gq, MQKV);
    }
    // Stage 3: attention (smem row-staged)
    {
        dim3 grid(H_, NH*ND, B_);
        attn_kernel<<<grid, 256, ATT_SMEM>>>();
    }
    // Stage 4: projection (192 x 192 x 16384 per batch)
    {
        dim3 grid(P_/GBN, C_/GBM, B_);
        gemm_mma<<<grid, 256>>>(gwp, go, out, C_);
    }
}